// round 5
// baseline (speedup 1.0000x reference)
#include <cuda_runtime.h>

#define V_SIZE 50000
#define B_SIZE 256
#define D_SIZE 64
#define NCTX   8

typedef unsigned long long ull;

// Scratch (allocation-free rule: __device__ globals)
__device__ int   g_ids[NCTX * B_SIZE];
__device__ __align__(16) float g_h[B_SIZE * D_SIZE];   // h[b][d]
__device__ float g_sumexp[B_SIZE];

// ---------------------------------------------------------------------------
// K1: find the nonzero in each one-hot row (unchanged from R4 — ~50us,
// issue-bound near its floor; early exit reads ~2/3 of the row).
// ---------------------------------------------------------------------------
__global__ void __launch_bounds__(512) k_scan(const float* __restrict__ x) {
    __shared__ int done;
    if (threadIdx.x == 0) done = 0;
    __syncthreads();

    int row = blockIdx.x;
    const uint4* p = (const uint4*)(x + (size_t)row * V_SIZE);
    int t = threadIdx.x;

    #pragma unroll 1
    for (int b = 0; b < 3; b++) {
        if (*(volatile int*)&done) return;
        int base = t + b * 4096;
        uint4 q0 = p[base        ];
        uint4 q1 = p[base +  512];
        uint4 q2 = p[base + 1024];
        uint4 q3 = p[base + 1536];
        uint4 q4 = p[base + 2048];
        uint4 q5 = p[base + 2560];
        uint4 q6 = p[base + 3072];
        uint4 q7 = p[base + 3584];
        unsigned o = q0.x|q0.y|q0.z|q0.w | q1.x|q1.y|q1.z|q1.w
                   | q2.x|q2.y|q2.z|q2.w | q3.x|q3.y|q3.z|q3.w
                   | q4.x|q4.y|q4.z|q4.w | q5.x|q5.y|q5.z|q5.w
                   | q6.x|q6.y|q6.z|q6.w | q7.x|q7.y|q7.z|q7.w;
        if (o != 0u) {
            uint4 qq[8] = {q0,q1,q2,q3,q4,q5,q6,q7};
            #pragma unroll
            for (int j = 0; j < 8; j++) {
                int c = 4 * (base + j * 512);
                if (qq[j].x) g_ids[row] = c + 0;
                if (qq[j].y) g_ids[row] = c + 1;
                if (qq[j].z) g_ids[row] = c + 2;
                if (qq[j].w) g_ids[row] = c + 3;
            }
            done = 1;
        }
    }
    if (t < 212 && !*(volatile int*)&done) {
        int base = 12288 + t;
        uint4 q = p[base];
        if (q.x|q.y|q.z|q.w) {
            int c = 4 * base;
            if (q.x) g_ids[row] = c + 0;
            if (q.y) g_ids[row] = c + 1;
            if (q.z) g_ids[row] = c + 2;
            if (q.w) g_ids[row] = c + 3;
        }
    }
}

// ---------------------------------------------------------------------------
// K2: h[b][d] = b1[d] + (1/8) * sum_i w1[d, ids[i][b]]
// ---------------------------------------------------------------------------
__global__ void __launch_bounds__(64) k_h(const float* __restrict__ w1,
                                          const float* __restrict__ b1) {
    int b = blockIdx.x, d = threadIdx.x;
    float acc = 0.0f;
    #pragma unroll
    for (int i = 0; i < NCTX; i++) {
        int id = g_ids[i * B_SIZE + b];
        acc += w1[(size_t)d * V_SIZE + id];
    }
    g_h[b * D_SIZE + d] = acc * (1.0f / NCTX) + b1[d];
}

// ---------------------------------------------------------------------------
// K3 (slot 3): zero accumulators (keeps k_gemm as the 4th, profiled, launch)
// ---------------------------------------------------------------------------
__global__ void k_zero() { g_sumexp[threadIdx.x] = 0.0f; }

// ---------------------------------------------------------------------------
// K4: logits[b][v] = dot(h[b,:], w2[v,:]) + b2[v], fused sum-of-exp per row.
// VPT=2: thread t handles v0 = blk*256+t and v1 = v0+128.
// All 64-bit packed loads (longlong2 -> ld.{global,shared}.v2.u64, no movs),
// fma.rn.f32x2, 4 independent accumulator chains. One 5-SHFL reduce per bb
// covers 64 vocab columns.
// ---------------------------------------------------------------------------
#define GEMM_T 128
#define VPT    2
#define BCHUNK 128
__global__ void __launch_bounds__(GEMM_T, 3) k_gemm(const float* __restrict__ w2,
                                                    const float* __restrict__ b2,
                                                    float* __restrict__ out) {
    __shared__ __align__(16) ull  hs[BCHUNK * 32];      // 32KB
    __shared__ float wsum[BCHUNK * 4];

    int t = threadIdx.x;
    int lane = t & 31, warp = t >> 5;
    int v0 = blockIdx.x * (GEMM_T * VPT) + t;
    int v1 = v0 + GEMM_T;
    bool act0 = v0 < V_SIZE, act1 = v1 < V_SIZE;
    int vc0 = act0 ? v0 : (V_SIZE - 1);
    int vc1 = act1 ? v1 : (V_SIZE - 1);

    ull w0r[32], w1r[32];
    {
        const longlong2* wp0 = (const longlong2*)(w2 + (size_t)vc0 * D_SIZE);
        const longlong2* wp1 = (const longlong2*)(w2 + (size_t)vc1 * D_SIZE);
        #pragma unroll
        for (int i = 0; i < 16; i++) {
            longlong2 a = wp0[i];
            longlong2 b = wp1[i];
            w0r[2*i] = (ull)a.x; w0r[2*i+1] = (ull)a.y;
            w1r[2*i] = (ull)b.x; w1r[2*i+1] = (ull)b.y;
        }
    }
    float b2v0 = __ldg(&b2[vc0]);
    float b2v1 = __ldg(&b2[vc1]);

    #pragma unroll 1
    for (int c = 0; c < B_SIZE / BCHUNK; c++) {
        __syncthreads();
        {   // stage h chunk: 128 rows x 256B = 2048 uint4
            const uint4* hg = (const uint4*)(g_h + c * BCHUNK * D_SIZE);
            uint4* hs4 = (uint4*)hs;
            #pragma unroll
            for (int i = 0; i < (BCHUNK * 32 / 2) / GEMM_T; i++)
                hs4[t + i * GEMM_T] = hg[t + i * GEMM_T];
        }
        __syncthreads();

        #pragma unroll 1
        for (int bb = 0; bb < BCHUNK; bb++) {
            const longlong2* hrow = (const longlong2*)&hs[bb * 32];
            ull a0 = 0ull, a1 = 0ull, c0 = 0ull, c1 = 0ull;
            #pragma unroll
            for (int k = 0; k < 16; k++) {
                longlong2 hh = hrow[k];
                ull h01 = (ull)hh.x, h23 = (ull)hh.y;
                asm("fma.rn.f32x2 %0, %1, %2, %0;" : "+l"(a0) : "l"(w0r[2*k]),   "l"(h01));
                asm("fma.rn.f32x2 %0, %1, %2, %0;" : "+l"(c0) : "l"(w1r[2*k]),   "l"(h01));
                asm("fma.rn.f32x2 %0, %1, %2, %0;" : "+l"(a1) : "l"(w0r[2*k+1]), "l"(h23));
                asm("fma.rn.f32x2 %0, %1, %2, %0;" : "+l"(c1) : "l"(w1r[2*k+1]), "l"(h23));
            }
            ull s0, s1;
            asm("add.rn.f32x2 %0, %1, %2;" : "=l"(s0) : "l"(a0), "l"(a1));
            asm("add.rn.f32x2 %0, %1, %2;" : "=l"(s1) : "l"(c0), "l"(c1));
            float x0, y0, x1, y1;
            asm("mov.b64 {%0,%1}, %2;" : "=f"(x0), "=f"(y0) : "l"(s0));
            asm("mov.b64 {%0,%1}, %2;" : "=f"(x1), "=f"(y1) : "l"(s1));
            float logit0 = x0 + y0 + b2v0;
            float logit1 = x1 + y1 + b2v1;

            float e = (act0 ? __expf(logit0) : 0.0f) + (act1 ? __expf(logit1) : 0.0f);
            #pragma unroll
            for (int off = 16; off > 0; off >>= 1)
                e += __shfl_xor_sync(0xffffffffu, e, off);
            if (lane == 0) wsum[bb * 4 + warp] = e;

            size_t rowoff = (size_t)(c * BCHUNK + bb) * V_SIZE;
            if (act0) out[rowoff + v0] = logit0;
            if (act1) out[rowoff + v1] = logit1;
        }
        __syncthreads();
        if (t < BCHUNK) {
            float s = wsum[t*4+0] + wsum[t*4+1] + wsum[t*4+2] + wsum[t*4+3];
            atomicAdd(&g_sumexp[c * BCHUNK + t], s);
        }
    }
}

// ---------------------------------------------------------------------------
// K5: out[b][v] -= log(sumexp[b])   (in-place; reads mostly L2-resident)
// ---------------------------------------------------------------------------
__global__ void __launch_bounds__(256) k_sub(float* __restrict__ out) {
    int b = blockIdx.y;
    int i = blockIdx.x * 256 + threadIdx.x;
    if (i < V_SIZE / 4) {
        float lse = __logf(g_sumexp[b]);
        float4* p = (float4*)(out + (size_t)b * V_SIZE);
        float4 x = p[i];
        x.x -= lse; x.y -= lse; x.z -= lse; x.w -= lse;
        p[i] = x;
    }
}

// ---------------------------------------------------------------------------
extern "C" void kernel_launch(void* const* d_in, const int* in_sizes, int n_in,
                              void* d_out, int out_size) {
    const float* x  = (const float*)d_in[0];   // [8, 256, 50000] one-hot
    const float* w1 = (const float*)d_in[1];   // [64, 50000]
    const float* b1 = (const float*)d_in[2];   // [64]
    const float* w2 = (const float*)d_in[3];   // [50000, 64]
    const float* b2 = (const float*)d_in[4];   // [50000]
    float* out = (float*)d_out;                // [256, 50000]

    k_scan<<<NCTX * B_SIZE, 512>>>(x);
    k_h<<<B_SIZE, D_SIZE>>>(w1, b1);
    k_zero<<<1, B_SIZE>>>();
    k_gemm<<<(V_SIZE + GEMM_T * VPT - 1) / (GEMM_T * VPT), GEMM_T>>>(w2, b2, out);
    k_sub<<<dim3((V_SIZE / 4 + 255) / 256, B_SIZE), 256>>>(out);
}

// round 6
// speedup vs baseline: 1.1472x; 1.1472x over previous
#include <cuda_runtime.h>

#define V_SIZE 50000
#define B_SIZE 256
#define D_SIZE 64
#define NCTX   8

typedef unsigned long long ull;

// Scratch (allocation-free rule: __device__ globals)
__device__ int   g_ids[NCTX * B_SIZE];
__device__ __align__(16) float g_h[B_SIZE * D_SIZE];   // h[b][d]
__device__ float g_sumexp[B_SIZE];

// ---------------------------------------------------------------------------
// K1: find the nonzero in each one-hot row (R4 version — near its floor)
// ---------------------------------------------------------------------------
__global__ void __launch_bounds__(512) k_scan(const float* __restrict__ x) {
    __shared__ int done;
    if (threadIdx.x == 0) done = 0;
    __syncthreads();

    int row = blockIdx.x;
    const uint4* p = (const uint4*)(x + (size_t)row * V_SIZE);
    int t = threadIdx.x;

    #pragma unroll 1
    for (int b = 0; b < 3; b++) {
        if (*(volatile int*)&done) return;
        int base = t + b * 4096;
        uint4 q0 = p[base        ];
        uint4 q1 = p[base +  512];
        uint4 q2 = p[base + 1024];
        uint4 q3 = p[base + 1536];
        uint4 q4 = p[base + 2048];
        uint4 q5 = p[base + 2560];
        uint4 q6 = p[base + 3072];
        uint4 q7 = p[base + 3584];
        unsigned o = q0.x|q0.y|q0.z|q0.w | q1.x|q1.y|q1.z|q1.w
                   | q2.x|q2.y|q2.z|q2.w | q3.x|q3.y|q3.z|q3.w
                   | q4.x|q4.y|q4.z|q4.w | q5.x|q5.y|q5.z|q5.w
                   | q6.x|q6.y|q6.z|q6.w | q7.x|q7.y|q7.z|q7.w;
        if (o != 0u) {
            uint4 qq[8] = {q0,q1,q2,q3,q4,q5,q6,q7};
            #pragma unroll
            for (int j = 0; j < 8; j++) {
                int c = 4 * (base + j * 512);
                if (qq[j].x) g_ids[row] = c + 0;
                if (qq[j].y) g_ids[row] = c + 1;
                if (qq[j].z) g_ids[row] = c + 2;
                if (qq[j].w) g_ids[row] = c + 3;
            }
            done = 1;
        }
    }
    if (t < 212 && !*(volatile int*)&done) {
        int base = 12288 + t;
        uint4 q = p[base];
        if (q.x|q.y|q.z|q.w) {
            int c = 4 * base;
            if (q.x) g_ids[row] = c + 0;
            if (q.y) g_ids[row] = c + 1;
            if (q.z) g_ids[row] = c + 2;
            if (q.w) g_ids[row] = c + 3;
        }
    }
}

// ---------------------------------------------------------------------------
// K2: h[b][d] = b1[d] + (1/8) * sum_i w1[d, ids[i][b]]
// ---------------------------------------------------------------------------
__global__ void __launch_bounds__(64) k_h(const float* __restrict__ w1,
                                          const float* __restrict__ b1) {
    int b = blockIdx.x, d = threadIdx.x;
    float acc = 0.0f;
    #pragma unroll
    for (int i = 0; i < NCTX; i++) {
        int id = g_ids[i * B_SIZE + b];
        acc += w1[(size_t)d * V_SIZE + id];
    }
    g_h[b * D_SIZE + d] = acc * (1.0f / NCTX) + b1[d];
}

// ---------------------------------------------------------------------------
// K3 (slot 3): zero accumulators (keeps k_gemm as the 4th, profiled, launch)
// ---------------------------------------------------------------------------
__global__ void k_zero() { g_sumexp[threadIdx.x] = 0.0f; }

// ---------------------------------------------------------------------------
// K4: logits[b][v] = dot(h[b,:], w2[v,:]) + b2[v], fused sum-of-exp.
// VPT=1 (R4 shape: 120 regs, 4 CTAs/SM). Deferred softmax reduction:
// per bb one fire-and-forget STS into ebuf; every 16 bbs a cooperative
// reduction (4 independent shuffle chains per warp, overlapped) + one
// no-return atomicAdd. The serial SHFL latency is paid once per 16 bbs
// instead of on every bb's critical path.
// ---------------------------------------------------------------------------
#define GEMM_T 128
#define BCHUNK 128
#define EGRP   16
__global__ void __launch_bounds__(GEMM_T, 4) k_gemm(const float* __restrict__ w2,
                                                    const float* __restrict__ b2,
                                                    float* __restrict__ out) {
    __shared__ __align__(16) ull   hs[BCHUNK * 32];     // 32KB
    __shared__ float ebuf[EGRP][GEMM_T];                // 8KB

    int t = threadIdx.x;
    int lane = t & 31, warp = t >> 5;
    int v = blockIdx.x * GEMM_T + t;
    bool active = v < V_SIZE;
    int vc = active ? v : (V_SIZE - 1);

    ull wreg[32];
    {
        const longlong2* wp = (const longlong2*)(w2 + (size_t)vc * D_SIZE);
        #pragma unroll
        for (int i = 0; i < 16; i++) {
            longlong2 a = wp[i];
            wreg[2*i] = (ull)a.x; wreg[2*i+1] = (ull)a.y;
        }
    }
    float b2v = __ldg(&b2[vc]);

    #pragma unroll 1
    for (int c = 0; c < B_SIZE / BCHUNK; c++) {
        __syncthreads();
        {   // stage h chunk: 128 rows x 256B = 2048 uint4
            const uint4* hg = (const uint4*)(g_h + c * BCHUNK * D_SIZE);
            uint4* hs4 = (uint4*)hs;
            #pragma unroll
            for (int i = 0; i < (BCHUNK * 32 / 2) / GEMM_T; i++)
                hs4[t + i * GEMM_T] = hg[t + i * GEMM_T];
        }
        __syncthreads();

        float* orow = out + (size_t)c * BCHUNK * V_SIZE + v;

        #pragma unroll 1
        for (int bb = 0; bb < BCHUNK; bb++) {
            const longlong2* hrow = (const longlong2*)&hs[bb * 32];
            ull a0 = 0ull, a1 = 0ull;
            #pragma unroll
            for (int k = 0; k < 16; k++) {
                longlong2 hh = hrow[k];
                ull h01 = (ull)hh.x, h23 = (ull)hh.y;
                asm("fma.rn.f32x2 %0, %1, %2, %0;" : "+l"(a0) : "l"(wreg[2*k]),   "l"(h01));
                asm("fma.rn.f32x2 %0, %1, %2, %0;" : "+l"(a1) : "l"(wreg[2*k+1]), "l"(h23));
            }
            ull s;
            asm("add.rn.f32x2 %0, %1, %2;" : "=l"(s) : "l"(a0), "l"(a1));
            float x0, y0;
            asm("mov.b64 {%0,%1}, %2;" : "=f"(x0), "=f"(y0) : "l"(s));
            float logit = x0 + y0 + b2v;

            ebuf[bb & (EGRP - 1)][t] = active ? __expf(logit) : 0.0f;
            if (active) *orow = logit;
            orow += V_SIZE;

            if ((bb & (EGRP - 1)) == EGRP - 1) {
                __syncthreads();
                #pragma unroll
                for (int rr = 0; rr < EGRP / 4; rr++) {
                    int row = warp * (EGRP / 4) + rr;
                    float s2 = ebuf[row][lane] + ebuf[row][lane + 32]
                             + ebuf[row][lane + 64] + ebuf[row][lane + 96];
                    #pragma unroll
                    for (int off = 16; off > 0; off >>= 1)
                        s2 += __shfl_xor_sync(0xffffffffu, s2, off);
                    if (lane == 0)
                        atomicAdd(&g_sumexp[c * BCHUNK + (bb & ~(EGRP - 1)) + row], s2);
                }
                __syncthreads();
            }
        }
    }
}

// ---------------------------------------------------------------------------
// K5: out[b][v] -= log(sumexp[b])   (in-place)
// ---------------------------------------------------------------------------
__global__ void __launch_bounds__(256) k_sub(float* __restrict__ out) {
    int b = blockIdx.y;
    int i = blockIdx.x * 256 + threadIdx.x;
    if (i < V_SIZE / 4) {
        float lse = __logf(g_sumexp[b]);
        float4* p = (float4*)(out + (size_t)b * V_SIZE);
        float4 x = p[i];
        x.x -= lse; x.y -= lse; x.z -= lse; x.w -= lse;
        p[i] = x;
    }
}

// ---------------------------------------------------------------------------
extern "C" void kernel_launch(void* const* d_in, const int* in_sizes, int n_in,
                              void* d_out, int out_size) {
    const float* x  = (const float*)d_in[0];   // [8, 256, 50000] one-hot
    const float* w1 = (const float*)d_in[1];   // [64, 50000]
    const float* b1 = (const float*)d_in[2];   // [64]
    const float* w2 = (const float*)d_in[3];   // [50000, 64]
    const float* b2 = (const float*)d_in[4];   // [50000]
    float* out = (float*)d_out;                // [256, 50000]

    k_scan<<<NCTX * B_SIZE, 512>>>(x);
    k_h<<<B_SIZE, D_SIZE>>>(w1, b1);
    k_zero<<<1, B_SIZE>>>();
    k_gemm<<<(V_SIZE + GEMM_T - 1) / GEMM_T, GEMM_T>>>(w2, b2, out);   // 4th: profiled
    k_sub<<<dim3((V_SIZE / 4 + 255) / 256, B_SIZE), 256>>>(out);
}

// round 8
// speedup vs baseline: 1.8168x; 1.5836x over previous
#include <cuda_runtime.h>
#include <cuda_bf16.h>
#include <cstdint>

#define V_SIZE 50000
#define B_SIZE 256
#define D_SIZE 64
#define NCTX   8
#define NT     128
#define V_TILES ((V_SIZE + NT - 1) / NT)     // 391
#define V_PAD   (V_TILES * NT)               // 50048
#define SSTR    72                           // padded shared row stride (bf16)

typedef unsigned long long ull;

// Scratch (allocation-free rule: __device__ globals)
__device__ int   g_ids[NCTX * B_SIZE];
__device__ __align__(16) __nv_bfloat16 g_hb[B_SIZE * D_SIZE];         // h bf16 [b][d]
__device__ __align__(16) __nv_bfloat16 g_w2b[(size_t)V_PAD * D_SIZE]; // w2 bf16, pad rows 0
__device__ float g_sumexp[B_SIZE];

// ---------------------------------------------------------------------------
// K1: find the nonzero in each one-hot row (unchanged — near its floor)
// ---------------------------------------------------------------------------
__global__ void __launch_bounds__(512) k_scan(const float* __restrict__ x) {
    __shared__ int done;
    if (threadIdx.x == 0) done = 0;
    __syncthreads();

    int row = blockIdx.x;
    const uint4* p = (const uint4*)(x + (size_t)row * V_SIZE);
    int t = threadIdx.x;

    #pragma unroll 1
    for (int b = 0; b < 3; b++) {
        if (*(volatile int*)&done) return;
        int base = t + b * 4096;
        uint4 q0 = p[base        ];
        uint4 q1 = p[base +  512];
        uint4 q2 = p[base + 1024];
        uint4 q3 = p[base + 1536];
        uint4 q4 = p[base + 2048];
        uint4 q5 = p[base + 2560];
        uint4 q6 = p[base + 3072];
        uint4 q7 = p[base + 3584];
        unsigned o = q0.x|q0.y|q0.z|q0.w | q1.x|q1.y|q1.z|q1.w
                   | q2.x|q2.y|q2.z|q2.w | q3.x|q3.y|q3.z|q3.w
                   | q4.x|q4.y|q4.z|q4.w | q5.x|q5.y|q5.z|q5.w
                   | q6.x|q6.y|q6.z|q6.w | q7.x|q7.y|q7.z|q7.w;
        if (o != 0u) {
            uint4 qq[8] = {q0,q1,q2,q3,q4,q5,q6,q7};
            #pragma unroll
            for (int j = 0; j < 8; j++) {
                int c = 4 * (base + j * 512);
                if (qq[j].x) g_ids[row] = c + 0;
                if (qq[j].y) g_ids[row] = c + 1;
                if (qq[j].z) g_ids[row] = c + 2;
                if (qq[j].w) g_ids[row] = c + 3;
            }
            done = 1;
        }
    }
    if (t < 212 && !*(volatile int*)&done) {
        int base = 12288 + t;
        uint4 q = p[base];
        if (q.x|q.y|q.z|q.w) {
            int c = 4 * base;
            if (q.x) g_ids[row] = c + 0;
            if (q.y) g_ids[row] = c + 1;
            if (q.z) g_ids[row] = c + 2;
            if (q.w) g_ids[row] = c + 3;
        }
    }
}

// ---------------------------------------------------------------------------
// K2: h[b][d] = b1[d] + (1/8) * sum_i w1[d, ids[i][b]]  -> bf16
// ---------------------------------------------------------------------------
__global__ void __launch_bounds__(64) k_h(const float* __restrict__ w1,
                                          const float* __restrict__ b1) {
    int b = blockIdx.x, d = threadIdx.x;
    float acc = 0.0f;
    #pragma unroll
    for (int i = 0; i < NCTX; i++) {
        int id = g_ids[i * B_SIZE + b];
        acc += w1[(size_t)d * V_SIZE + id];
    }
    g_hb[b * D_SIZE + d] = __float2bfloat16(acc * (1.0f / NCTX) + b1[d]);
}

// ---------------------------------------------------------------------------
// K3: w2 fp32 -> bf16 (padded to V_PAD rows, pad = 0); zero g_sumexp.
// ---------------------------------------------------------------------------
__global__ void __launch_bounds__(256) k_cvt(const float* __restrict__ w2) {
    if (blockIdx.x == 0 && threadIdx.x < B_SIZE) g_sumexp[threadIdx.x] = 0.0f;
    size_t i = (size_t)blockIdx.x * 256 + threadIdx.x;
    size_t e = i * 8;
    uint4 o = make_uint4(0u, 0u, 0u, 0u);
    if (e < (size_t)V_SIZE * D_SIZE) {
        const float4* s = (const float4*)(w2 + e);
        float4 f0 = s[0], f1 = s[1];
        __nv_bfloat162 p0 = __float22bfloat162_rn(make_float2(f0.x, f0.y));
        __nv_bfloat162 p1 = __float22bfloat162_rn(make_float2(f0.z, f0.w));
        __nv_bfloat162 p2 = __float22bfloat162_rn(make_float2(f1.x, f1.y));
        __nv_bfloat162 p3 = __float22bfloat162_rn(make_float2(f1.z, f1.w));
        o.x = *(uint32_t*)&p0; o.y = *(uint32_t*)&p1;
        o.z = *(uint32_t*)&p2; o.w = *(uint32_t*)&p3;
    }
    if (e < (size_t)V_PAD * D_SIZE) ((uint4*)g_w2b)[i] = o;
}

// ---------------------------------------------------------------------------
// K4: warp-MMA gemm [M=128(b) x N=128(v) x K=64] via mma.sync.m16n8k16.bf16
// (baseline PTX — no 'a'-target needed). 8 warps, warp w owns b-rows
// [w*16, w*16+16). Shared staging with stride-72 rows => conflict-free
// fragment LDS. Fused epilogue: +b2 (-inf pad), expf, 4-lane shuffle,
// 1 atomicAdd per b-row per warp, float2 stores.
// ---------------------------------------------------------------------------
__global__ void __launch_bounds__(256) k_mma(const float* __restrict__ b2,
                                             float* __restrict__ out) {
    __shared__ __align__(16) __nv_bfloat16 sa[128 * SSTR];   // h tile
    __shared__ __align__(16) __nv_bfloat16 sb[NT * SSTR];    // w2 tile
    int t = threadIdx.x, lane = t & 31, w = t >> 5;
    int g = lane >> 2, t4 = lane & 3;
    int vt = blockIdx.x, bh = blockIdx.y;

    {   // stage A and B: 1024 uint4 each, row stride 72 bf16 (144B, 16B-aligned)
        const uint4* as = (const uint4*)(g_hb + bh * 128 * D_SIZE);
        const uint4* bs = (const uint4*)(g_w2b + (size_t)vt * NT * D_SIZE);
        #pragma unroll
        for (int i = 0; i < 4; i++) {
            int idx = i * 256 + t;               // 0..1023
            int row = idx >> 3, col = (idx & 7) * 8;
            *(uint4*)&sa[row * SSTR + col] = as[idx];
            *(uint4*)&sb[row * SSTR + col] = bs[idx];
        }
    }
    __syncthreads();

    // A fragments: rows w*16+g and +8, cols t4*2 + {0,8} + 16*kk
    uint32_t aF[4][4];
    {
        const __nv_bfloat16* pa = sa + (w * 16 + g) * SSTR + t4 * 2;
        #pragma unroll
        for (int kk = 0; kk < 4; kk++) {
            aF[kk][0] = *(const uint32_t*)(pa + kk * 16);
            aF[kk][1] = *(const uint32_t*)(pa + 8 * SSTR + kk * 16);
            aF[kk][2] = *(const uint32_t*)(pa + kk * 16 + 8);
            aF[kk][3] = *(const uint32_t*)(pa + 8 * SSTR + kk * 16 + 8);
        }
    }

    float acc[16][4];
    #pragma unroll
    for (int nt = 0; nt < 16; nt++)
        acc[nt][0] = acc[nt][1] = acc[nt][2] = acc[nt][3] = 0.0f;

    #pragma unroll
    for (int nt = 0; nt < 16; nt++) {
        const __nv_bfloat16* pb = sb + (nt * 8 + g) * SSTR + t4 * 2;
        #pragma unroll
        for (int kk = 0; kk < 4; kk++) {
            uint32_t b0 = *(const uint32_t*)(pb + kk * 16);
            uint32_t b1 = *(const uint32_t*)(pb + kk * 16 + 8);
            asm volatile(
                "mma.sync.aligned.m16n8k16.row.col.f32.bf16.bf16.f32 "
                "{%0,%1,%2,%3}, {%4,%5,%6,%7}, {%8,%9}, {%0,%1,%2,%3};"
                : "+f"(acc[nt][0]), "+f"(acc[nt][1]),
                  "+f"(acc[nt][2]), "+f"(acc[nt][3])
                : "r"(aF[kk][0]), "r"(aF[kk][1]), "r"(aF[kk][2]), "r"(aF[kk][3]),
                  "r"(b0), "r"(b1));
        }
    }

    // Epilogue: rows b0r/b1r, cols v..v+1 per n-tile
    int b0r = bh * 128 + w * 16 + g;
    int b1r = b0r + 8;
    int vbase = vt * NT + t4 * 2;
    float* o0 = out + (size_t)b0r * V_SIZE;
    float* o1 = out + (size_t)b1r * V_SIZE;
    const float NEG_INF = __int_as_float(0xff800000);
    float e0 = 0.0f, e1 = 0.0f;
    #pragma unroll
    for (int nt = 0; nt < 16; nt++) {
        int v = vbase + nt * 8;
        bool act = v < V_SIZE;                    // v even, V even -> pair-atomic
        float2 bias = act ? *(const float2*)(b2 + v) : make_float2(NEG_INF, NEG_INF);
        float l00 = acc[nt][0] + bias.x, l01 = acc[nt][1] + bias.y;
        float l10 = acc[nt][2] + bias.x, l11 = acc[nt][3] + bias.y;
        e0 += __expf(l00) + __expf(l01);
        e1 += __expf(l10) + __expf(l11);
        if (act) {
            *(float2*)(o0 + v) = make_float2(l00, l01);
            *(float2*)(o1 + v) = make_float2(l10, l11);
        }
    }
    // reduce across the 4 lanes sharing a row (t4 = 0..3)
    e0 += __shfl_xor_sync(0xffffffffu, e0, 1);
    e0 += __shfl_xor_sync(0xffffffffu, e0, 2);
    e1 += __shfl_xor_sync(0xffffffffu, e1, 1);
    e1 += __shfl_xor_sync(0xffffffffu, e1, 2);
    if (t4 == 0) {
        atomicAdd(&g_sumexp[b0r], e0);
        atomicAdd(&g_sumexp[b1r], e1);
    }
}

// ---------------------------------------------------------------------------
// K5: out[b][v] -= log(sumexp[b])   (in-place)
// ---------------------------------------------------------------------------
__global__ void __launch_bounds__(256) k_sub(float* __restrict__ out) {
    int b = blockIdx.y;
    int i = blockIdx.x * 256 + threadIdx.x;
    if (i < V_SIZE / 4) {
        float lse = __logf(g_sumexp[b]);
        float4* p = (float4*)(out + (size_t)b * V_SIZE);
        float4 x = p[i];
        x.x -= lse; x.y -= lse; x.z -= lse; x.w -= lse;
        p[i] = x;
    }
}

// ---------------------------------------------------------------------------
extern "C" void kernel_launch(void* const* d_in, const int* in_sizes, int n_in,
                              void* d_out, int out_size) {
    const float* x  = (const float*)d_in[0];   // [8, 256, 50000] one-hot
    const float* w1 = (const float*)d_in[1];   // [64, 50000]
    const float* b1 = (const float*)d_in[2];   // [64]
    const float* w2 = (const float*)d_in[3];   // [50000, 64]
    const float* b2 = (const float*)d_in[4];   // [50000]
    float* out = (float*)d_out;                // [256, 50000]

    k_scan<<<NCTX * B_SIZE, 512>>>(x);
    k_h<<<B_SIZE, D_SIZE>>>(w1, b1);
    k_cvt<<<(int)(((size_t)V_PAD * D_SIZE / 8 + 255) / 256), 256>>>(w2);
    k_mma<<<dim3(V_TILES, 2), 256>>>(b2, out);   // 4th launch: profiled
    k_sub<<<dim3((V_SIZE / 4 + 255) / 256, B_SIZE), 256>>>(out);
}

// round 9
// speedup vs baseline: 1.9429x; 1.0694x over previous
#include <cuda_runtime.h>
#include <cuda_bf16.h>
#include <cuda_fp16.h>
#include <cstdint>

#define V_SIZE 50000
#define B_SIZE 256
#define D_SIZE 64
#define NCTX   8
#define NT     128
#define V_TILES ((V_SIZE + NT - 1) / NT)     // 391
#define V_PAD   (V_TILES * NT)               // 50048
#define SSTR    72                           // padded shared row stride (bf16)

// Scratch (allocation-free rule: __device__ globals)
__device__ int   g_ids[NCTX * B_SIZE];
__device__ __align__(16) __nv_bfloat16 g_hb[B_SIZE * D_SIZE];         // h bf16 [b][d]
__device__ __align__(16) __nv_bfloat16 g_w2b[(size_t)V_PAD * D_SIZE]; // w2 bf16, pad rows 0
__device__ float g_sumexp[B_SIZE];

// ---------------------------------------------------------------------------
// K1: find the nonzero in each one-hot row. 6 batches x 4 uint4 -> finer
// early exit (expected bytes 0.58 of row vs 0.67 with 3x8).
// ---------------------------------------------------------------------------
__global__ void __launch_bounds__(512) k_scan(const float* __restrict__ x) {
    __shared__ int done;
    if (threadIdx.x == 0) done = 0;
    __syncthreads();

    int row = blockIdx.x;
    const uint4* p = (const uint4*)(x + (size_t)row * V_SIZE);
    int t = threadIdx.x;

    #pragma unroll 1
    for (int b = 0; b < 6; b++) {
        if (*(volatile int*)&done) return;
        int base = t + b * 2048;             // 512 threads * 4 chunks
        uint4 q0 = p[base        ];
        uint4 q1 = p[base +  512];
        uint4 q2 = p[base + 1024];
        uint4 q3 = p[base + 1536];
        unsigned o = q0.x|q0.y|q0.z|q0.w | q1.x|q1.y|q1.z|q1.w
                   | q2.x|q2.y|q2.z|q2.w | q3.x|q3.y|q3.z|q3.w;
        if (o != 0u) {                       // slow path: once per row
            uint4 qq[4] = {q0,q1,q2,q3};
            #pragma unroll
            for (int j = 0; j < 4; j++) {
                int c = 4 * (base + j * 512);
                if (qq[j].x) g_ids[row] = c + 0;
                if (qq[j].y) g_ids[row] = c + 1;
                if (qq[j].z) g_ids[row] = c + 2;
                if (qq[j].w) g_ids[row] = c + 3;
            }
            done = 1;
        }
    }
    // tail: chunks 12288..12499
    if (t < 212 && !*(volatile int*)&done) {
        int base = 12288 + t;
        uint4 q = p[base];
        if (q.x|q.y|q.z|q.w) {
            int c = 4 * base;
            if (q.x) g_ids[row] = c + 0;
            if (q.y) g_ids[row] = c + 1;
            if (q.z) g_ids[row] = c + 2;
            if (q.w) g_ids[row] = c + 3;
        }
    }
}

// ---------------------------------------------------------------------------
// K2: h[b][d] = b1[d] + (1/8) * sum_i w1[d, ids[i][b]]  -> bf16
// ---------------------------------------------------------------------------
__global__ void __launch_bounds__(64) k_h(const float* __restrict__ w1,
                                          const float* __restrict__ b1) {
    int b = blockIdx.x, d = threadIdx.x;
    float acc = 0.0f;
    #pragma unroll
    for (int i = 0; i < NCTX; i++) {
        int id = g_ids[i * B_SIZE + b];
        acc += w1[(size_t)d * V_SIZE + id];
    }
    g_hb[b * D_SIZE + d] = __float2bfloat16(acc * (1.0f / NCTX) + b1[d]);
}

// ---------------------------------------------------------------------------
// K3: w2 fp32 -> bf16 (padded to V_PAD rows, pad = 0); zero g_sumexp.
// ---------------------------------------------------------------------------
__global__ void __launch_bounds__(256) k_cvt(const float* __restrict__ w2) {
    if (blockIdx.x == 0 && threadIdx.x < B_SIZE) g_sumexp[threadIdx.x] = 0.0f;
    size_t i = (size_t)blockIdx.x * 256 + threadIdx.x;
    size_t e = i * 8;
    uint4 o = make_uint4(0u, 0u, 0u, 0u);
    if (e < (size_t)V_SIZE * D_SIZE) {
        const float4* s = (const float4*)(w2 + e);
        float4 f0 = s[0], f1 = s[1];
        __nv_bfloat162 p0 = __float22bfloat162_rn(make_float2(f0.x, f0.y));
        __nv_bfloat162 p1 = __float22bfloat162_rn(make_float2(f0.z, f0.w));
        __nv_bfloat162 p2 = __float22bfloat162_rn(make_float2(f1.x, f1.y));
        __nv_bfloat162 p3 = __float22bfloat162_rn(make_float2(f1.z, f1.w));
        o.x = *(uint32_t*)&p0; o.y = *(uint32_t*)&p1;
        o.z = *(uint32_t*)&p2; o.w = *(uint32_t*)&p3;
    }
    if (e < (size_t)V_PAD * D_SIZE) ((uint4*)g_w2b)[i] = o;
}

// ---------------------------------------------------------------------------
// Shared MMA core: computes acc[nt][0..3] for a [128b x 128v x 64] tile.
// Warp w owns b-rows [w*16, w*16+16); fragments from stride-72 smem.
// ---------------------------------------------------------------------------
struct MmaAcc { float a[16][4]; };

__device__ __forceinline__ void mma_tile(const __nv_bfloat16* __restrict__ ha,
                                         const __nv_bfloat16* __restrict__ wb,
                                         int t, int lane, int w, MmaAcc& A) {
    __shared__ __align__(16) __nv_bfloat16 sa[128 * SSTR];
    __shared__ __align__(16) __nv_bfloat16 sb[NT * SSTR];
    int g = lane >> 2, t4 = lane & 3;

    const uint4* as = (const uint4*)ha;
    const uint4* bs = (const uint4*)wb;
    #pragma unroll
    for (int i = 0; i < 4; i++) {
        int idx = i * 256 + t;
        int row = idx >> 3, col = (idx & 7) * 8;
        *(uint4*)&sa[row * SSTR + col] = as[idx];
        *(uint4*)&sb[row * SSTR + col] = bs[idx];
    }
    __syncthreads();

    uint32_t aF[4][4];
    {
        const __nv_bfloat16* pa = sa + (w * 16 + g) * SSTR + t4 * 2;
        #pragma unroll
        for (int kk = 0; kk < 4; kk++) {
            aF[kk][0] = *(const uint32_t*)(pa + kk * 16);
            aF[kk][1] = *(const uint32_t*)(pa + 8 * SSTR + kk * 16);
            aF[kk][2] = *(const uint32_t*)(pa + kk * 16 + 8);
            aF[kk][3] = *(const uint32_t*)(pa + 8 * SSTR + kk * 16 + 8);
        }
    }
    #pragma unroll
    for (int nt = 0; nt < 16; nt++)
        A.a[nt][0] = A.a[nt][1] = A.a[nt][2] = A.a[nt][3] = 0.0f;
    #pragma unroll
    for (int nt = 0; nt < 16; nt++) {
        const __nv_bfloat16* pb = sb + (nt * 8 + g) * SSTR + t4 * 2;
        #pragma unroll
        for (int kk = 0; kk < 4; kk++) {
            uint32_t b0 = *(const uint32_t*)(pb + kk * 16);
            uint32_t b1 = *(const uint32_t*)(pb + kk * 16 + 8);
            asm volatile(
                "mma.sync.aligned.m16n8k16.row.col.f32.bf16.bf16.f32 "
                "{%0,%1,%2,%3}, {%4,%5,%6,%7}, {%8,%9}, {%0,%1,%2,%3};"
                : "+f"(A.a[nt][0]), "+f"(A.a[nt][1]),
                  "+f"(A.a[nt][2]), "+f"(A.a[nt][3])
                : "r"(aF[kk][0]), "r"(aF[kk][1]), "r"(aF[kk][2]), "r"(aF[kk][3]),
                  "r"(b0), "r"(b1));
        }
    }
}

// ---------------------------------------------------------------------------
// K4 (pass 1): sumexp only — NO logit stores. exp via h2exp (f16x2):
// half the MUFU ops, HADD2 accumulation (values ~1, chains of 16: safe).
// Pad columns: bias = -inf -> h2exp -> 0.
// ---------------------------------------------------------------------------
__global__ void __launch_bounds__(256) k_mma1(const float* __restrict__ b2) {
    int t = threadIdx.x, lane = t & 31, w = t >> 5;
    int g = lane >> 2, t4 = lane & 3;
    int vt = blockIdx.x, bh = blockIdx.y;

    MmaAcc A;
    mma_tile(g_hb + bh * 128 * D_SIZE, g_w2b + (size_t)vt * NT * D_SIZE,
             t, lane, w, A);

    int vbase = vt * NT + t4 * 2;
    const float NEG_INF = __int_as_float(0xff800000);
    __half2 ea = __floats2half2_rn(0.0f, 0.0f);
    __half2 eb = __floats2half2_rn(0.0f, 0.0f);
    #pragma unroll
    for (int nt = 0; nt < 16; nt++) {
        int v = vbase + nt * 8;
        float2 bias = (v < V_SIZE) ? *(const float2*)(b2 + v)
                                   : make_float2(NEG_INF, NEG_INF);
        ea = __hadd2(ea, h2exp(__floats2half2_rn(A.a[nt][0] + bias.x,
                                                 A.a[nt][1] + bias.y)));
        eb = __hadd2(eb, h2exp(__floats2half2_rn(A.a[nt][2] + bias.x,
                                                 A.a[nt][3] + bias.y)));
    }
    float2 f0 = __half22float2(ea);
    float2 f1 = __half22float2(eb);
    float e0 = f0.x + f0.y, e1 = f1.x + f1.y;
    e0 += __shfl_xor_sync(0xffffffffu, e0, 1);
    e0 += __shfl_xor_sync(0xffffffffu, e0, 2);
    e1 += __shfl_xor_sync(0xffffffffu, e1, 1);
    e1 += __shfl_xor_sync(0xffffffffu, e1, 2);
    if (t4 == 0) {
        atomicAdd(&g_sumexp[bh * 128 + w * 16 + g], e0);
        atomicAdd(&g_sumexp[bh * 128 + w * 16 + g + 8], e1);
    }
}

// ---------------------------------------------------------------------------
// K5 (pass 2): recompute MMA, store FINAL log_softmax = logit - lse directly.
// lse staged per-CTA in smem (128 __logf per CTA). No exp, no k_sub.
// ---------------------------------------------------------------------------
__global__ void __launch_bounds__(256) k_mma2(const float* __restrict__ b2,
                                              float* __restrict__ out) {
    __shared__ float lse_s[128];
    int t = threadIdx.x, lane = t & 31, w = t >> 5;
    int g = lane >> 2, t4 = lane & 3;
    int vt = blockIdx.x, bh = blockIdx.y;

    if (t < 128) lse_s[t] = __logf(g_sumexp[bh * 128 + t]);
    // (mma_tile's __syncthreads covers lse_s visibility)

    MmaAcc A;
    mma_tile(g_hb + bh * 128 * D_SIZE, g_w2b + (size_t)vt * NT * D_SIZE,
             t, lane, w, A);

    float lse0 = lse_s[w * 16 + g];
    float lse1 = lse_s[w * 16 + g + 8];
    int b0r = bh * 128 + w * 16 + g;
    int vbase = vt * NT + t4 * 2;
    float* o0 = out + (size_t)b0r * V_SIZE;
    float* o1 = o0 + (size_t)8 * V_SIZE;
    #pragma unroll
    for (int nt = 0; nt < 16; nt++) {
        int v = vbase + nt * 8;
        if (v < V_SIZE) {
            float2 bias = *(const float2*)(b2 + v);
            *(float2*)(o0 + v) = make_float2(A.a[nt][0] + bias.x - lse0,
                                             A.a[nt][1] + bias.y - lse0);
            *(float2*)(o1 + v) = make_float2(A.a[nt][2] + bias.x - lse1,
                                             A.a[nt][3] + bias.y - lse1);
        }
    }
}

// ---------------------------------------------------------------------------
extern "C" void kernel_launch(void* const* d_in, const int* in_sizes, int n_in,
                              void* d_out, int out_size) {
    const float* x  = (const float*)d_in[0];   // [8, 256, 50000] one-hot
    const float* w1 = (const float*)d_in[1];   // [64, 50000]
    const float* b1 = (const float*)d_in[2];   // [64]
    const float* w2 = (const float*)d_in[3];   // [50000, 64]
    const float* b2 = (const float*)d_in[4];   // [50000]
    float* out = (float*)d_out;                // [256, 50000]

    k_scan<<<NCTX * B_SIZE, 512>>>(x);
    k_h<<<B_SIZE, D_SIZE>>>(w1, b1);
    k_cvt<<<(int)(((size_t)V_PAD * D_SIZE / 8 + 255) / 256), 256>>>(w2);
    k_mma1<<<dim3(V_TILES, 2), 256>>>(b2);          // 4th launch: profiled
    k_mma2<<<dim3(V_TILES, 2), 256>>>(b2, out);
}

// round 10
// speedup vs baseline: 2.0511x; 1.0557x over previous
#include <cuda_runtime.h>
#include <cuda_bf16.h>
#include <cuda_fp16.h>
#include <cstdint>

#define V_SIZE 50000
#define B_SIZE 256
#define D_SIZE 64
#define NCTX   8
#define NT     128
#define V_TILES ((V_SIZE + NT - 1) / NT)     // 391
#define SSTR    72                           // padded shared row stride (bf16)

// Scratch (allocation-free rule: __device__ globals)
__device__ int   g_ids[NCTX * B_SIZE];
__device__ __align__(16) __nv_bfloat16 g_hb[B_SIZE * D_SIZE];   // h bf16 [b][d]
__device__ float g_sumexp[B_SIZE];

// ---------------------------------------------------------------------------
// K1: find the nonzero in each one-hot row. 12 batches x 2 uint4 per thread:
// early-exit granularity 8.2% of row -> expected bytes ~0.54 of 409.6MB.
// ---------------------------------------------------------------------------
__global__ void __launch_bounds__(512) k_scan(const float* __restrict__ x) {
    __shared__ int done;
    if (threadIdx.x == 0) done = 0;
    __syncthreads();

    int row = blockIdx.x;
    const uint4* p = (const uint4*)(x + (size_t)row * V_SIZE);
    int t = threadIdx.x;

    #pragma unroll 1
    for (int b = 0; b < 12; b++) {
        if (*(volatile int*)&done) return;
        int base = t + b * 1024;             // 512 threads * 2 chunks
        uint4 q0 = p[base      ];
        uint4 q1 = p[base + 512];
        unsigned o = q0.x|q0.y|q0.z|q0.w | q1.x|q1.y|q1.z|q1.w;
        if (o != 0u) {                       // slow path: once per row
            uint4 qq[2] = {q0, q1};
            #pragma unroll
            for (int j = 0; j < 2; j++) {
                int c = 4 * (base + j * 512);
                if (qq[j].x) g_ids[row] = c + 0;
                if (qq[j].y) g_ids[row] = c + 1;
                if (qq[j].z) g_ids[row] = c + 2;
                if (qq[j].w) g_ids[row] = c + 3;
            }
            done = 1;
        }
    }
    // tail: chunks 12288..12499
    if (t < 212 && !*(volatile int*)&done) {
        int base = 12288 + t;
        uint4 q = p[base];
        if (q.x|q.y|q.z|q.w) {
            int c = 4 * base;
            if (q.x) g_ids[row] = c + 0;
            if (q.y) g_ids[row] = c + 1;
            if (q.z) g_ids[row] = c + 2;
            if (q.w) g_ids[row] = c + 3;
        }
    }
}

// ---------------------------------------------------------------------------
// K2: h[b][d] = b1[d] + (1/8) * sum_i w1[d, ids[i][b]] -> bf16; zero sumexp.
// ---------------------------------------------------------------------------
__global__ void __launch_bounds__(64) k_h(const float* __restrict__ w1,
                                          const float* __restrict__ b1) {
    int b = blockIdx.x, d = threadIdx.x;
    if (d == 0) g_sumexp[b] = 0.0f;
    float acc = 0.0f;
    #pragma unroll
    for (int i = 0; i < NCTX; i++) {
        int id = g_ids[i * B_SIZE + b];
        acc += w1[(size_t)d * V_SIZE + id];
    }
    g_hb[b * D_SIZE + d] = __float2bfloat16(acc * (1.0f / NCTX) + b1[d]);
}

// ---------------------------------------------------------------------------
// Shared MMA core: [128b x 128v x 64] tile via mma.sync.m16n8k16.bf16.
// A (h) staged from bf16 global; B (w2) staged DIRECTLY from fp32 global with
// inline bf16 conversion (no separate cvt kernel; vrow>=V_SIZE -> zeros).
// Warp w owns b-rows [w*16, w*16+16); stride-72 smem = conflict-free frags.
// ---------------------------------------------------------------------------
struct MmaAcc { float a[16][4]; };

__device__ __forceinline__ void mma_tile(const __nv_bfloat16* __restrict__ ha,
                                         const float* __restrict__ w2, int vt,
                                         int t, int lane, int w, MmaAcc& A) {
    __shared__ __align__(16) __nv_bfloat16 sa[128 * SSTR];
    __shared__ __align__(16) __nv_bfloat16 sb[NT * SSTR];
    int g = lane >> 2, t4 = lane & 3;

    {   // A: 1024 uint4 (bf16)
        const uint4* as = (const uint4*)ha;
        #pragma unroll
        for (int i = 0; i < 4; i++) {
            int idx = i * 256 + t;
            int row = idx >> 3, col = (idx & 7) * 8;
            *(uint4*)&sa[row * SSTR + col] = as[idx];
        }
    }
    {   // B: 2048 float4 (fp32) -> bf16x2 pairs
        #pragma unroll
        for (int i = 0; i < 8; i++) {
            int idx = i * 256 + t;               // 0..2047
            int row = idx >> 4, colf = (idx & 15) * 4;
            int vrow = vt * NT + row;
            float4 f = (vrow < V_SIZE)
                     ? *(const float4*)(w2 + (size_t)vrow * D_SIZE + colf)
                     : make_float4(0.f, 0.f, 0.f, 0.f);
            __nv_bfloat162 lo = __float22bfloat162_rn(make_float2(f.x, f.y));
            __nv_bfloat162 hi = __float22bfloat162_rn(make_float2(f.z, f.w));
            uint2 pk;
            pk.x = *(uint32_t*)&lo; pk.y = *(uint32_t*)&hi;
            *(uint2*)&sb[row * SSTR + colf] = pk;
        }
    }
    __syncthreads();

    uint32_t aF[4][4];
    {
        const __nv_bfloat16* pa = sa + (w * 16 + g) * SSTR + t4 * 2;
        #pragma unroll
        for (int kk = 0; kk < 4; kk++) {
            aF[kk][0] = *(const uint32_t*)(pa + kk * 16);
            aF[kk][1] = *(const uint32_t*)(pa + 8 * SSTR + kk * 16);
            aF[kk][2] = *(const uint32_t*)(pa + kk * 16 + 8);
            aF[kk][3] = *(const uint32_t*)(pa + 8 * SSTR + kk * 16 + 8);
        }
    }
    #pragma unroll
    for (int nt = 0; nt < 16; nt++)
        A.a[nt][0] = A.a[nt][1] = A.a[nt][2] = A.a[nt][3] = 0.0f;
    #pragma unroll
    for (int nt = 0; nt < 16; nt++) {
        const __nv_bfloat16* pb = sb + (nt * 8 + g) * SSTR + t4 * 2;
        #pragma unroll
        for (int kk = 0; kk < 4; kk++) {
            uint32_t b0 = *(const uint32_t*)(pb + kk * 16);
            uint32_t b1 = *(const uint32_t*)(pb + kk * 16 + 8);
            asm volatile(
                "mma.sync.aligned.m16n8k16.row.col.f32.bf16.bf16.f32 "
                "{%0,%1,%2,%3}, {%4,%5,%6,%7}, {%8,%9}, {%0,%1,%2,%3};"
                : "+f"(A.a[nt][0]), "+f"(A.a[nt][1]),
                  "+f"(A.a[nt][2]), "+f"(A.a[nt][3])
                : "r"(aF[kk][0]), "r"(aF[kk][1]), "r"(aF[kk][2]), "r"(aF[kk][3]),
                  "r"(b0), "r"(b1));
        }
    }
}

// ---------------------------------------------------------------------------
// K3 (pass 1): sumexp only — no logit stores. exp via h2exp (f16x2).
// Pad columns: bias = -inf -> h2exp -> 0.
// ---------------------------------------------------------------------------
__global__ void __launch_bounds__(256) k_mma1(const float* __restrict__ w2,
                                              const float* __restrict__ b2) {
    int t = threadIdx.x, lane = t & 31, w = t >> 5;
    int g = lane >> 2, t4 = lane & 3;
    int vt = blockIdx.x, bh = blockIdx.y;

    MmaAcc A;
    mma_tile(g_hb + bh * 128 * D_SIZE, w2, vt, t, lane, w, A);

    int vbase = vt * NT + t4 * 2;
    const float NEG_INF = __int_as_float(0xff800000);
    __half2 ea = __floats2half2_rn(0.0f, 0.0f);
    __half2 eb = __floats2half2_rn(0.0f, 0.0f);
    #pragma unroll
    for (int nt = 0; nt < 16; nt++) {
        int v = vbase + nt * 8;
        float2 bias = (v < V_SIZE) ? *(const float2*)(b2 + v)
                                   : make_float2(NEG_INF, NEG_INF);
        ea = __hadd2(ea, h2exp(__floats2half2_rn(A.a[nt][0] + bias.x,
                                                 A.a[nt][1] + bias.y)));
        eb = __hadd2(eb, h2exp(__floats2half2_rn(A.a[nt][2] + bias.x,
                                                 A.a[nt][3] + bias.y)));
    }
    float2 f0 = __half22float2(ea);
    float2 f1 = __half22float2(eb);
    float e0 = f0.x + f0.y, e1 = f1.x + f1.y;
    e0 += __shfl_xor_sync(0xffffffffu, e0, 1);
    e0 += __shfl_xor_sync(0xffffffffu, e0, 2);
    e1 += __shfl_xor_sync(0xffffffffu, e1, 1);
    e1 += __shfl_xor_sync(0xffffffffu, e1, 2);
    if (t4 == 0) {
        atomicAdd(&g_sumexp[bh * 128 + w * 16 + g], e0);
        atomicAdd(&g_sumexp[bh * 128 + w * 16 + g + 8], e1);
    }
}

// ---------------------------------------------------------------------------
// K4 (pass 2): recompute MMA, store FINAL log_softmax = logit - lse directly.
// ---------------------------------------------------------------------------
__global__ void __launch_bounds__(256) k_mma2(const float* __restrict__ w2,
                                              const float* __restrict__ b2,
                                              float* __restrict__ out) {
    __shared__ float lse_s[128];
    int t = threadIdx.x, lane = t & 31, w = t >> 5;
    int g = lane >> 2, t4 = lane & 3;
    int vt = blockIdx.x, bh = blockIdx.y;

    if (t < 128) lse_s[t] = __logf(g_sumexp[bh * 128 + t]);
    // (mma_tile's __syncthreads covers lse_s visibility)

    MmaAcc A;
    mma_tile(g_hb + bh * 128 * D_SIZE, w2, vt, t, lane, w, A);

    float lse0 = lse_s[w * 16 + g];
    float lse1 = lse_s[w * 16 + g + 8];
    int b0r = bh * 128 + w * 16 + g;
    int vbase = vt * NT + t4 * 2;
    float* o0 = out + (size_t)b0r * V_SIZE;
    float* o1 = o0 + (size_t)8 * V_SIZE;
    #pragma unroll
    for (int nt = 0; nt < 16; nt++) {
        int v = vbase + nt * 8;
        if (v < V_SIZE) {
            float2 bias = *(const float2*)(b2 + v);
            *(float2*)(o0 + v) = make_float2(A.a[nt][0] + bias.x - lse0,
                                             A.a[nt][1] + bias.y - lse0);
            *(float2*)(o1 + v) = make_float2(A.a[nt][2] + bias.x - lse1,
                                             A.a[nt][3] + bias.y - lse1);
        }
    }
}

// ---------------------------------------------------------------------------
extern "C" void kernel_launch(void* const* d_in, const int* in_sizes, int n_in,
                              void* d_out, int out_size) {
    const float* x  = (const float*)d_in[0];   // [8, 256, 50000] one-hot
    const float* w1 = (const float*)d_in[1];   // [64, 50000]
    const float* b1 = (const float*)d_in[2];   // [64]
    const float* w2 = (const float*)d_in[3];   // [50000, 64]
    const float* b2 = (const float*)d_in[4];   // [50000]
    float* out = (float*)d_out;                // [256, 50000]

    k_scan<<<NCTX * B_SIZE, 512>>>(x);
    k_h<<<B_SIZE, D_SIZE>>>(w1, b1);
    k_mma1<<<dim3(V_TILES, 2), 256>>>(w2, b2);
    k_mma2<<<dim3(V_TILES, 2), 256>>>(w2, b2, out);   // 4th launch: profiled
}

// round 11
// speedup vs baseline: 2.1140x; 1.0307x over previous
#include <cuda_runtime.h>
#include <cuda_bf16.h>
#include <cuda_fp16.h>
#include <cstdint>

#define V_SIZE 50000
#define B_SIZE 256
#define D_SIZE 64
#define NCTX   8
#define NT     128
#define V_TILES ((V_SIZE + NT - 1) / NT)     // 391
#define SSTR    72                           // padded shared row stride (bf16)

// Scratch (allocation-free rule: __device__ globals)
__device__ int   g_ids[NCTX * B_SIZE];
__device__ __align__(16) __nv_bfloat16 g_hb[B_SIZE * D_SIZE];   // h bf16 [b][d]
__device__ float g_sumexp[B_SIZE];

// ---------------------------------------------------------------------------
// K1: find the nonzero in each one-hot row (12 batches x 2 uint4, early exit)
// ---------------------------------------------------------------------------
__global__ void __launch_bounds__(512) k_scan(const float* __restrict__ x) {
    __shared__ int done;
    if (threadIdx.x == 0) done = 0;
    __syncthreads();

    int row = blockIdx.x;
    const uint4* p = (const uint4*)(x + (size_t)row * V_SIZE);
    int t = threadIdx.x;

    #pragma unroll 1
    for (int b = 0; b < 12; b++) {
        if (*(volatile int*)&done) return;
        int base = t + b * 1024;
        uint4 q0 = p[base      ];
        uint4 q1 = p[base + 512];
        unsigned o = q0.x|q0.y|q0.z|q0.w | q1.x|q1.y|q1.z|q1.w;
        if (o != 0u) {
            uint4 qq[2] = {q0, q1};
            #pragma unroll
            for (int j = 0; j < 2; j++) {
                int c = 4 * (base + j * 512);
                if (qq[j].x) g_ids[row] = c + 0;
                if (qq[j].y) g_ids[row] = c + 1;
                if (qq[j].z) g_ids[row] = c + 2;
                if (qq[j].w) g_ids[row] = c + 3;
            }
            done = 1;
        }
    }
    if (t < 212 && !*(volatile int*)&done) {
        int base = 12288 + t;
        uint4 q = p[base];
        if (q.x|q.y|q.z|q.w) {
            int c = 4 * base;
            if (q.x) g_ids[row] = c + 0;
            if (q.y) g_ids[row] = c + 1;
            if (q.z) g_ids[row] = c + 2;
            if (q.w) g_ids[row] = c + 3;
        }
    }
}

// ---------------------------------------------------------------------------
// K2: h[b][d] = b1[d] + (1/8) * sum_i w1[d, ids[i][b]] -> bf16; zero sumexp.
// ---------------------------------------------------------------------------
__global__ void __launch_bounds__(64) k_h(const float* __restrict__ w1,
                                          const float* __restrict__ b1) {
    int b = blockIdx.x, d = threadIdx.x;
    if (d == 0) g_sumexp[b] = 0.0f;
    float acc = 0.0f;
    #pragma unroll
    for (int i = 0; i < NCTX; i++) {
        int id = g_ids[i * B_SIZE + b];
        acc += w1[(size_t)d * V_SIZE + id];
    }
    g_hb[b * D_SIZE + d] = __float2bfloat16(acc * (1.0f / NCTX) + b1[d]);
}

// ---------------------------------------------------------------------------
// MMA helpers. CTA owns one v-tile; stages B (w2, inline fp32->bf16) ONCE,
// then loops bh in {0,1} restaging only the 4KB A tile.
// Warp w owns b-rows [w*16, w*16+16) of the 128-row half; stride-72 smem.
// ---------------------------------------------------------------------------
struct MmaAcc { float a[16][4]; };

__device__ __forceinline__ void stage_b(__nv_bfloat16* sb,
                                        const float* __restrict__ w2,
                                        int vt, int t) {
    #pragma unroll
    for (int i = 0; i < 8; i++) {
        int idx = i * 256 + t;               // 0..2047
        int row = idx >> 4, colf = (idx & 15) * 4;
        int vrow = vt * NT + row;
        float4 f = (vrow < V_SIZE)
                 ? *(const float4*)(w2 + (size_t)vrow * D_SIZE + colf)
                 : make_float4(0.f, 0.f, 0.f, 0.f);
        __nv_bfloat162 lo = __float22bfloat162_rn(make_float2(f.x, f.y));
        __nv_bfloat162 hi = __float22bfloat162_rn(make_float2(f.z, f.w));
        uint2 pk;
        pk.x = *(uint32_t*)&lo; pk.y = *(uint32_t*)&hi;
        *(uint2*)&sb[row * SSTR + colf] = pk;
    }
}

__device__ __forceinline__ void stage_a(__nv_bfloat16* sa,
                                        const __nv_bfloat16* __restrict__ ha,
                                        int t) {
    const uint4* as = (const uint4*)ha;
    #pragma unroll
    for (int i = 0; i < 4; i++) {
        int idx = i * 256 + t;
        int row = idx >> 3, col = (idx & 7) * 8;
        *(uint4*)&sa[row * SSTR + col] = as[idx];
    }
}

__device__ __forceinline__ void do_mma(const __nv_bfloat16* sa,
                                       const __nv_bfloat16* sb,
                                       int w, int g, int t4, MmaAcc& A) {
    uint32_t aF[4][4];
    {
        const __nv_bfloat16* pa = sa + (w * 16 + g) * SSTR + t4 * 2;
        #pragma unroll
        for (int kk = 0; kk < 4; kk++) {
            aF[kk][0] = *(const uint32_t*)(pa + kk * 16);
            aF[kk][1] = *(const uint32_t*)(pa + 8 * SSTR + kk * 16);
            aF[kk][2] = *(const uint32_t*)(pa + kk * 16 + 8);
            aF[kk][3] = *(const uint32_t*)(pa + 8 * SSTR + kk * 16 + 8);
        }
    }
    #pragma unroll
    for (int nt = 0; nt < 16; nt++)
        A.a[nt][0] = A.a[nt][1] = A.a[nt][2] = A.a[nt][3] = 0.0f;
    #pragma unroll
    for (int nt = 0; nt < 16; nt++) {
        const __nv_bfloat16* pb = sb + (nt * 8 + g) * SSTR + t4 * 2;
        #pragma unroll
        for (int kk = 0; kk < 4; kk++) {
            uint32_t b0 = *(const uint32_t*)(pb + kk * 16);
            uint32_t b1 = *(const uint32_t*)(pb + kk * 16 + 8);
            asm volatile(
                "mma.sync.aligned.m16n8k16.row.col.f32.bf16.bf16.f32 "
                "{%0,%1,%2,%3}, {%4,%5,%6,%7}, {%8,%9}, {%0,%1,%2,%3};"
                : "+f"(A.a[nt][0]), "+f"(A.a[nt][1]),
                  "+f"(A.a[nt][2]), "+f"(A.a[nt][3])
                : "r"(aF[kk][0]), "r"(aF[kk][1]), "r"(aF[kk][2]), "r"(aF[kk][3]),
                  "r"(b0), "r"(b1));
        }
    }
}

// ---------------------------------------------------------------------------
// K3 (pass 1): sumexp only — no logit stores. exp via h2exp (f16x2).
// ---------------------------------------------------------------------------
__global__ void __launch_bounds__(256) k_mma1(const float* __restrict__ w2,
                                              const float* __restrict__ b2) {
    __shared__ __align__(16) __nv_bfloat16 sa[128 * SSTR];
    __shared__ __align__(16) __nv_bfloat16 sb[NT * SSTR];
    int t = threadIdx.x, lane = t & 31, w = t >> 5;
    int g = lane >> 2, t4 = lane & 3;
    int vt = blockIdx.x;

    stage_b(sb, w2, vt, t);

    const float NEG_INF = __int_as_float(0xff800000);
    #pragma unroll 1
    for (int bh = 0; bh < 2; bh++) {
        if (bh) __syncthreads();             // all aF reads of prev sa done
        stage_a(sa, g_hb + bh * 128 * D_SIZE, t);
        __syncthreads();

        MmaAcc A;
        do_mma(sa, sb, w, g, t4, A);

        int vbase = vt * NT + t4 * 2;
        __half2 ea = __floats2half2_rn(0.0f, 0.0f);
        __half2 eb = __floats2half2_rn(0.0f, 0.0f);
        #pragma unroll
        for (int nt = 0; nt < 16; nt++) {
            int v = vbase + nt * 8;
            float2 bias = (v < V_SIZE) ? *(const float2*)(b2 + v)
                                       : make_float2(NEG_INF, NEG_INF);
            ea = __hadd2(ea, h2exp(__floats2half2_rn(A.a[nt][0] + bias.x,
                                                     A.a[nt][1] + bias.y)));
            eb = __hadd2(eb, h2exp(__floats2half2_rn(A.a[nt][2] + bias.x,
                                                     A.a[nt][3] + bias.y)));
        }
        float2 f0 = __half22float2(ea);
        float2 f1 = __half22float2(eb);
        float e0 = f0.x + f0.y, e1 = f1.x + f1.y;
        e0 += __shfl_xor_sync(0xffffffffu, e0, 1);
        e0 += __shfl_xor_sync(0xffffffffu, e0, 2);
        e1 += __shfl_xor_sync(0xffffffffu, e1, 1);
        e1 += __shfl_xor_sync(0xffffffffu, e1, 2);
        if (t4 == 0) {
            atomicAdd(&g_sumexp[bh * 128 + w * 16 + g], e0);
            atomicAdd(&g_sumexp[bh * 128 + w * 16 + g + 8], e1);
        }
    }
}

// ---------------------------------------------------------------------------
// K4 (pass 2): recompute MMA, store FINAL log_softmax = logit - lse directly.
// ---------------------------------------------------------------------------
__global__ void __launch_bounds__(256) k_mma2(const float* __restrict__ w2,
                                              const float* __restrict__ b2,
                                              float* __restrict__ out) {
    __shared__ __align__(16) __nv_bfloat16 sa[128 * SSTR];
    __shared__ __align__(16) __nv_bfloat16 sb[NT * SSTR];
    __shared__ float lse_s[B_SIZE];
    int t = threadIdx.x, lane = t & 31, w = t >> 5;
    int g = lane >> 2, t4 = lane & 3;
    int vt = blockIdx.x;

    lse_s[t] = __logf(g_sumexp[t]);          // 256 threads, 256 rows
    stage_b(sb, w2, vt, t);

    #pragma unroll 1
    for (int bh = 0; bh < 2; bh++) {
        if (bh) __syncthreads();
        stage_a(sa, g_hb + bh * 128 * D_SIZE, t);
        __syncthreads();                      // also publishes lse_s (bh=0)

        MmaAcc A;
        do_mma(sa, sb, w, g, t4, A);

        int b0r = bh * 128 + w * 16 + g;
        float lse0 = lse_s[b0r];
        float lse1 = lse_s[b0r + 8];
        int vbase = vt * NT + t4 * 2;
        float* o0 = out + (size_t)b0r * V_SIZE;
        float* o1 = o0 + (size_t)8 * V_SIZE;
        #pragma unroll
        for (int nt = 0; nt < 16; nt++) {
            int v = vbase + nt * 8;
            if (v < V_SIZE) {
                float2 bias = *(const float2*)(b2 + v);
                *(float2*)(o0 + v) = make_float2(A.a[nt][0] + bias.x - lse0,
                                                 A.a[nt][1] + bias.y - lse0);
                *(float2*)(o1 + v) = make_float2(A.a[nt][2] + bias.x - lse1,
                                                 A.a[nt][3] + bias.y - lse1);
            }
        }
    }
}

// ---------------------------------------------------------------------------
extern "C" void kernel_launch(void* const* d_in, const int* in_sizes, int n_in,
                              void* d_out, int out_size) {
    const float* x  = (const float*)d_in[0];   // [8, 256, 50000] one-hot
    const float* w1 = (const float*)d_in[1];   // [64, 50000]
    const float* b1 = (const float*)d_in[2];   // [64]
    const float* w2 = (const float*)d_in[3];   // [50000, 64]
    const float* b2 = (const float*)d_in[4];   // [50000]
    float* out = (float*)d_out;                // [256, 50000]

    k_scan<<<NCTX * B_SIZE, 512>>>(x);
    k_h<<<B_SIZE, D_SIZE>>>(w1, b1);
    k_mma1<<<V_TILES, 256>>>(w2, b2);
    k_mma2<<<V_TILES, 256>>>(w2, b2, out);     // 4th launch: profiled
}